// round 2
// baseline (speedup 1.0000x reference)
#include <cuda_runtime.h>

#define N_NODES 100000
#define N_EDGES 640000
#define DD      128
#define ROUNDS  4
#define AS_STRIDE 129   // padded stride for transposed A tile (reduces STS conflicts)

// Scratch (allocation-free rule: __device__ globals). 16B-aligned for float4/red.v4.
__device__ __align__(16) float g_msg[N_NODES * DD];
__device__ __align__(16) float g_agg[N_NODES * DD];
__device__ int g_idx64;   // 1 if edge_index buffer is int64, 0 if int32

// ---- Detect edge_index dtype on-device (deterministic, ~0 cost) ----
__global__ void detect_idx_kernel(const int* __restrict__ ei32)
{
    int is64 = 1;
    for (int i = 0; i < 32; i++) {
        int lo = ei32[2 * i];
        int hi = ei32[2 * i + 1];
        if (hi != 0 || lo < 0 || lo >= N_NODES) { is64 = 0; break; }
    }
    g_idx64 = is64;
}

// out = relu(A @ W + bias)            (MODE == 0)
// out = out + relu(A @ W + bias)      (MODE == 1, residual update)
// A: [n,128] row-major, W: [128,128] row-major (k-major rows), bias: [128]
template <int MODE>
__global__ __launch_bounds__(256, 1) void gemm_relu_kernel(
    const float* __restrict__ A,
    const float* __restrict__ W,
    const float* __restrict__ bias,
    float* __restrict__ out,
    int n)
{
    extern __shared__ float sm[];
    float* As = sm;                      // As[k][m], stride AS_STRIDE (transposed A tile)
    float* Bs = sm + 128 * AS_STRIDE;    // Bs[k][nn], stride 128 (natural W layout)

    const int tid = threadIdx.x;         // 256 threads
    const int m0  = blockIdx.x * 128;

    // ---- Load W -> Bs (coalesced, conflict-free) ----
    {
        const float4* Wv = (const float4*)W;
        float4* Bv = (float4*)Bs;
#pragma unroll
        for (int i = 0; i < 16; i++)
            Bv[tid + i * 256] = Wv[tid + i * 256];
    }

    // ---- Load A tile (coalesced) and transpose into As ----
    {
#pragma unroll
        for (int i = 0; i < 16; i++) {
            int idx = tid + i * 256;     // 0..4095
            int m   = idx >> 5;          // 0..127 (row within tile)
            int k4  = idx & 31;          // float4 index along k
            int row = m0 + m;
            float4 v = make_float4(0.f, 0.f, 0.f, 0.f);
            if (row < n)
                v = *(const float4*)(A + (size_t)row * DD + k4 * 4);
            As[(k4 * 4 + 0) * AS_STRIDE + m] = v.x;
            As[(k4 * 4 + 1) * AS_STRIDE + m] = v.y;
            As[(k4 * 4 + 2) * AS_STRIDE + m] = v.z;
            As[(k4 * 4 + 3) * AS_STRIDE + m] = v.w;
        }
    }
    __syncthreads();

    const int tr = tid >> 4;             // 0..15 (row group)
    const int tc = tid & 15;             // 0..15 (col group)
    // Thread's 8 rows: tr*4+i (i<4) and 64+tr*4+(i-4); 8 cols: tc*4+j and 64+tc*4+j.

    float acc[8][8];
#pragma unroll
    for (int i = 0; i < 8; i++)
#pragma unroll
        for (int j = 0; j < 8; j++)
            acc[i][j] = 0.f;

#pragma unroll 4
    for (int k = 0; k < 128; k++) {
        const float* Ak = As + k * AS_STRIDE;
        const float* Bk = Bs + k * 128;
        float a[8], b[8];
#pragma unroll
        for (int i = 0; i < 4; i++) {
            a[i]     = Ak[tr * 4 + i];
            a[4 + i] = Ak[64 + tr * 4 + i];
        }
        float4 b0 = *(const float4*)(Bk + tc * 4);
        float4 b1 = *(const float4*)(Bk + 64 + tc * 4);
        b[0] = b0.x; b[1] = b0.y; b[2] = b0.z; b[3] = b0.w;
        b[4] = b1.x; b[5] = b1.y; b[6] = b1.z; b[7] = b1.w;
#pragma unroll
        for (int i = 0; i < 8; i++)
#pragma unroll
            for (int j = 0; j < 8; j++)
                acc[i][j] += a[i] * b[j];
    }

    // ---- Epilogue: bias + relu (+ residual) ----
    float4 bb0 = *(const float4*)(bias + tc * 4);
    float4 bb1 = *(const float4*)(bias + 64 + tc * 4);
    float bb[8] = {bb0.x, bb0.y, bb0.z, bb0.w, bb1.x, bb1.y, bb1.z, bb1.w};

#pragma unroll
    for (int i = 0; i < 8; i++) {
        int rloc = (i < 4) ? (tr * 4 + i) : (64 + tr * 4 + (i - 4));
        int row  = m0 + rloc;
        if (row >= n) continue;
        float* orow = out + (size_t)row * DD;

        float v[8];
#pragma unroll
        for (int j = 0; j < 8; j++) {
            float t = acc[i][j] + bb[j];
            v[j] = t > 0.f ? t : 0.f;
        }
        if (MODE == 1) {
            float4 o0 = *(float4*)(orow + tc * 4);
            float4 o1 = *(float4*)(orow + 64 + tc * 4);
            v[0] += o0.x; v[1] += o0.y; v[2] += o0.z; v[3] += o0.w;
            v[4] += o1.x; v[5] += o1.y; v[6] += o1.z; v[7] += o1.w;
        }
        *(float4*)(orow + tc * 4)      = make_float4(v[0], v[1], v[2], v[3]);
        *(float4*)(orow + 64 + tc * 4) = make_float4(v[4], v[5], v[6], v[7]);
    }
}

__global__ void zero_agg_kernel()
{
    int i = blockIdx.x * blockDim.x + threadIdx.x;   // 3.2M float4 slots
    ((float4*)g_agg)[i] = make_float4(0.f, 0.f, 0.f, 0.f);
}

// One warp per edge: gather 512B message row (L2-resident) and scatter-add via red.v4
__global__ __launch_bounds__(256) void scatter_kernel(const void* __restrict__ ei_raw)
{
    int w    = (blockIdx.x * 256 + threadIdx.x) >> 5;   // edge id
    int lane = threadIdx.x & 31;
    if (w >= N_EDGES) return;

    long long s, d;
    if (__ldg(&g_idx64)) {
        const long long* ei = (const long long*)ei_raw;
        s = __ldg(ei + w);
        d = __ldg(ei + N_EDGES + w);
    } else {
        const int* ei = (const int*)ei_raw;
        s = __ldg(ei + w);
        d = __ldg(ei + N_EDGES + w);
    }
    // Range guard: never fault even if dtype detection were wrong.
    if ((unsigned long long)s >= N_NODES || (unsigned long long)d >= N_NODES) return;

    float4 v = *(const float4*)(g_msg + (size_t)s * DD + lane * 4);
    float* p = g_agg + (size_t)d * DD + lane * 4;
    asm volatile("red.global.add.v4.f32 [%0], {%1,%2,%3,%4};"
                 :: "l"(p), "f"(v.x), "f"(v.y), "f"(v.z), "f"(v.w)
                 : "memory");
}

extern "C" void kernel_launch(void* const* d_in, const int* in_sizes, int n_in,
                              void* d_out, int out_size)
{
    const float* x  = (const float*)d_in[0];
    const void*  ei = d_in[1];
    const float* Wi = (const float*)d_in[2];
    const float* bi = (const float*)d_in[3];
    const float* Wm = (const float*)d_in[4];
    const float* bm = (const float*)d_in[5];
    const float* Wu = (const float*)d_in[6];
    const float* bu = (const float*)d_in[7];
    float* out = (float*)d_out;

    const size_t smem = (size_t)(128 * AS_STRIDE + 128 * 128) * sizeof(float);
    cudaFuncSetAttribute(gemm_relu_kernel<0>, cudaFuncAttributeMaxDynamicSharedMemorySize, (int)smem);
    cudaFuncSetAttribute(gemm_relu_kernel<1>, cudaFuncAttributeMaxDynamicSharedMemorySize, (int)smem);

    float *msg, *agg;
    cudaGetSymbolAddress((void**)&msg, g_msg);
    cudaGetSymbolAddress((void**)&agg, g_agg);

    dim3 grid((N_NODES + 127) / 128);

    detect_idx_kernel<<<1, 1>>>((const int*)ei);

    // state = relu(x @ Wi + bi)
    gemm_relu_kernel<0><<<grid, 256, smem>>>(x, Wi, bi, out, N_NODES);

    for (int r = 0; r < ROUNDS; r++) {
        // message = relu(state @ Wm_r + bm_r)
        gemm_relu_kernel<0><<<grid, 256, smem>>>(out, Wm + r * DD * DD, bm + r * DD, msg, N_NODES);
        // aggregated = segment_sum(message[src], dst)
        zero_agg_kernel<<<(N_NODES * DD / 4) / 256, 256>>>();
        scatter_kernel<<<(N_EDGES * 32) / 256, 256>>>(ei);
        // state = state + relu(aggregated @ Wu_r + bu_r)
        gemm_relu_kernel<1><<<grid, 256, smem>>>(agg, Wu + r * DD * DD, bu + r * DD, out, N_NODES);
    }
}

// round 4
// speedup vs baseline: 1.2109x; 1.2109x over previous
#include <cuda_runtime.h>
#include <cuda_bf16.h>
#include <cstdint>

#define N_NODES 100000
#define N_EDGES 640000
#define DD      128
#define ROUNDS  4

// ---------------- scratch (allocation-free rule: __device__ globals) ----------------
__device__ __align__(16) float g_msg[N_NODES * DD];
__device__ __align__(16) float g_agg[N_NODES * DD];
// 9 weight matrices, transposed [n][k], bf16 split: hi (16384) + lo (16384) each
__device__ __align__(16) __nv_bfloat16 g_wb[9 * 2 * 16384];
__device__ int g_idx64;

// ---------------- edge_index dtype detection ----------------
__global__ void detect_idx_kernel(const int* __restrict__ ei32) {
    int is64 = 1;
    for (int i = 0; i < 32; i++) {
        int lo = ei32[2 * i];
        int hi = ei32[2 * i + 1];
        if (hi != 0 || lo < 0 || lo >= N_NODES) { is64 = 0; break; }
    }
    g_idx64 = is64;
}

// ---------------- weight precompute: transpose + bf16 split ----------------
// g_wb[m] : hi[n][k] (128x128), lo[n][k]
__global__ void conv_w_kernel(const float* __restrict__ Wi,
                              const float* __restrict__ Wm,
                              const float* __restrict__ Wu) {
    int m = blockIdx.x;  // 0..8
    const float* W = (m == 0) ? Wi : (m <= 4 ? Wm + (m - 1) * DD * DD : Wu + (m - 5) * DD * DD);
    __nv_bfloat16* hi = g_wb + (size_t)m * 32768;
    __nv_bfloat16* lo = hi + 16384;
    for (int i = threadIdx.x; i < 2048; i += blockDim.x) {
        int nrow = i >> 4;          // output feature (row of B)
        int k8   = (i & 15) * 8;
        __align__(16) __nv_bfloat16 h[8], l[8];
#pragma unroll
        for (int j = 0; j < 8; j++) {
            float w = W[(size_t)(k8 + j) * DD + nrow];   // B[n][k] = W[k][n]
            __nv_bfloat16 hb = __float2bfloat16(w);
            h[j] = hb;
            l[j] = __float2bfloat16(w - __bfloat162float(hb));
        }
        *(uint4*)(hi + nrow * DD + k8) = *(const uint4*)h;
        *(uint4*)(lo + nrow * DD + k8) = *(const uint4*)l;
    }
}

// ---------------- helpers (base-target PTX only) ----------------
__device__ __forceinline__ uint32_t smem_u32(const void* p) {
    uint32_t a;
    asm("{ .reg .u64 t; cvta.to.shared.u64 t, %1; cvt.u32.u64 %0, t; }" : "=r"(a) : "l"(p));
    return a;
}
__device__ __forceinline__ void ldsm4(uint32_t& r0, uint32_t& r1, uint32_t& r2, uint32_t& r3,
                                      uint32_t addr) {
    asm volatile("ldmatrix.sync.aligned.m8n8.x4.shared.b16 {%0,%1,%2,%3}, [%4];"
                 : "=r"(r0), "=r"(r1), "=r"(r2), "=r"(r3) : "r"(addr));
}
__device__ __forceinline__ void mma_bf16(float& c0, float& c1, float& c2, float& c3,
                                         uint32_t a0, uint32_t a1, uint32_t a2, uint32_t a3,
                                         uint32_t b0, uint32_t b1) {
    asm volatile(
        "mma.sync.aligned.m16n8k16.row.col.f32.bf16.bf16.f32 "
        "{%0,%1,%2,%3}, {%4,%5,%6,%7}, {%8,%9}, {%0,%1,%2,%3};"
        : "+f"(c0), "+f"(c1), "+f"(c2), "+f"(c3)
        : "r"(a0), "r"(a1), "r"(a2), "r"(a3), "r"(b0), "r"(b1));
}

// ---------------- mma.sync GEMM: out = [out +] relu(A @ W + bias) ----------------
// SMEM: bias 512B | A_hi [128][136]bf16 | A_lo | B_hi [128n][136]bf16 | B_lo
#define BSTR    136                       // bf16 elems per row (272B = 17*16B, conflict-free)
#define TILE_B  (128 * BSTR * 2)          // 34816 B
#define SM_BIAS 0
#define SM_AHI  512
#define SM_ALO  (SM_AHI + TILE_B)
#define SM_BHI  (SM_ALO + TILE_B)
#define SM_BLO  (SM_BHI + TILE_B)
#define SM_TOTAL (SM_BLO + TILE_B)

template <int MODE>
__global__ __launch_bounds__(256, 1) void gemm_mma_kernel(
    const float* __restrict__ A,
    const __nv_bfloat16* __restrict__ wb,   // hi(16384) + lo(16384), [n][k]
    const float* __restrict__ bias,
    float* __restrict__ out,
    int n)
{
    extern __shared__ char smem[];
    const uint32_t sb = smem_u32(smem);
    const int tid = threadIdx.x, wid = tid >> 5, lane = tid & 31;
    const int wr = wid & 1, wc = wid >> 1;      // warp grid 2 (M) x 4 (N)
    const int m0 = blockIdx.x * 128;

    if (tid < 128) *(float*)(smem + SM_BIAS + tid * 4) = bias[tid];

    // ---- weights: global [n][128] -> smem [n][BSTR] (hi and lo) ----
    {
        const uint4* srch = (const uint4*)wb;            // 16 uint4 per row
        const uint4* srcl = (const uint4*)(wb + 16384);
#pragma unroll
        for (int i = tid; i < 2048; i += 256) {
            int row = i >> 4, c = i & 15;
            *(uint4*)(smem + SM_BHI + row * (BSTR * 2) + c * 16) = srch[row * 16 + c];
            *(uint4*)(smem + SM_BLO + row * (BSTR * 2) + c * 16) = srcl[row * 16 + c];
        }
    }

    // ---- A tile: fp32 -> bf16 hi/lo into smem [r][BSTR] ----
    for (int i = tid; i < 2048; i += 256) {
        int r  = i >> 4;
        int k8 = (i & 15) * 8;
        int row = m0 + r;
        float v[8];
        if (row < n) {
            float4 u0 = *(const float4*)(A + (size_t)row * DD + k8);
            float4 u1 = *(const float4*)(A + (size_t)row * DD + k8 + 4);
            v[0] = u0.x; v[1] = u0.y; v[2] = u0.z; v[3] = u0.w;
            v[4] = u1.x; v[5] = u1.y; v[6] = u1.z; v[7] = u1.w;
        } else {
#pragma unroll
            for (int j = 0; j < 8; j++) v[j] = 0.f;
        }
        __align__(16) __nv_bfloat16 h[8], l[8];
#pragma unroll
        for (int j = 0; j < 8; j++) {
            __nv_bfloat16 hb = __float2bfloat16(v[j]);
            h[j] = hb;
            l[j] = __float2bfloat16(v[j] - __bfloat162float(hb));
        }
        *(uint4*)(smem + SM_AHI + r * (BSTR * 2) + k8 * 2) = *(const uint4*)h;
        *(uint4*)(smem + SM_ALO + r * (BSTR * 2) + k8 * 2) = *(const uint4*)l;
    }
    __syncthreads();

    // ---- mainloop: 8 k-steps, 3 split passes fused per k-step ----
    float acc[4][4][4];                     // [mtile][ntile][reg]
#pragma unroll
    for (int t = 0; t < 4; t++)
#pragma unroll
        for (int j = 0; j < 4; j++)
#pragma unroll
            for (int q = 0; q < 4; q++)
                acc[t][j][q] = 0.f;

    // ldmatrix lane addressing (A: 16x16, x4; B: [n][k] non-trans, 16n x 16k, x4)
    const uint32_t a_row = (uint32_t)(wr * 64 + (lane & 15));
    const uint32_t a_colh = (uint32_t)(lane >> 4);           // 0/1 -> +8 cols
    const uint32_t b_nrow = (uint32_t)(wc * 32 + (lane & 7) + ((lane >> 4) << 3));
    const uint32_t b_kh   = (uint32_t)((lane >> 3) & 1);     // 0/1 -> +8 k

#pragma unroll
    for (int ks = 0; ks < 8; ks++) {
        uint32_t ah[4][4], al[4][4], bh[2][4], bl[2][4];
        const uint32_t kcol = (uint32_t)(ks * 16);
#pragma unroll
        for (int t = 0; t < 4; t++) {
            uint32_t off = (a_row + t * 16) * (BSTR * 2) + (kcol + a_colh * 8) * 2;
            ldsm4(ah[t][0], ah[t][1], ah[t][2], ah[t][3], sb + SM_AHI + off);
            ldsm4(al[t][0], al[t][1], al[t][2], al[t][3], sb + SM_ALO + off);
        }
#pragma unroll
        for (int p = 0; p < 2; p++) {
            uint32_t off = (b_nrow + p * 16) * (BSTR * 2) + (kcol + b_kh * 8) * 2;
            ldsm4(bh[p][0], bh[p][1], bh[p][2], bh[p][3], sb + SM_BHI + off);
            ldsm4(bl[p][0], bl[p][1], bl[p][2], bl[p][3], sb + SM_BLO + off);
        }
#pragma unroll
        for (int t = 0; t < 4; t++) {
#pragma unroll
            for (int j = 0; j < 4; j++) {
                uint32_t bh0 = bh[j >> 1][(j & 1) * 2], bh1 = bh[j >> 1][(j & 1) * 2 + 1];
                uint32_t bl0 = bl[j >> 1][(j & 1) * 2], bl1 = bl[j >> 1][(j & 1) * 2 + 1];
                float* c = acc[t][j];
                mma_bf16(c[0], c[1], c[2], c[3], ah[t][0], ah[t][1], ah[t][2], ah[t][3], bh0, bh1);
                mma_bf16(c[0], c[1], c[2], c[3], ah[t][0], ah[t][1], ah[t][2], ah[t][3], bl0, bl1);
                mma_bf16(c[0], c[1], c[2], c[3], al[t][0], al[t][1], al[t][2], al[t][3], bh0, bh1);
            }
        }
    }

    // ---- epilogue: bias + relu (+ residual) ----
    const float* bs = (const float*)(smem + SM_BIAS);
#pragma unroll
    for (int t = 0; t < 4; t++) {
        int row0 = m0 + wr * 64 + t * 16 + (lane >> 2);
#pragma unroll
        for (int half = 0; half < 2; half++) {
            int row = row0 + half * 8;
            if (row >= n) continue;
            float* orow = out + (size_t)row * DD;
#pragma unroll
            for (int j = 0; j < 4; j++) {
                int col = wc * 32 + j * 8 + (lane & 3) * 2;
                float v0 = acc[t][j][half * 2 + 0] + bs[col];
                float v1 = acc[t][j][half * 2 + 1] + bs[col + 1];
                v0 = v0 > 0.f ? v0 : 0.f;
                v1 = v1 > 0.f ? v1 : 0.f;
                if (MODE == 1) {
                    float2 o = *(const float2*)(orow + col);
                    v0 += o.x; v1 += o.y;
                }
                *(float2*)(orow + col) = make_float2(v0, v1);
            }
        }
    }
}

// ---------------- scatter phase ----------------
__global__ void zero_agg_kernel() {
    int i = blockIdx.x * blockDim.x + threadIdx.x;
    ((float4*)g_agg)[i] = make_float4(0.f, 0.f, 0.f, 0.f);
}

__global__ __launch_bounds__(256) void scatter_kernel(const void* __restrict__ ei_raw) {
    int w    = (blockIdx.x * 256 + threadIdx.x) >> 5;
    int lane = threadIdx.x & 31;
    if (w >= N_EDGES) return;

    long long s, d;
    if (__ldg(&g_idx64)) {
        const long long* ei = (const long long*)ei_raw;
        s = __ldg(ei + w);
        d = __ldg(ei + N_EDGES + w);
    } else {
        const int* ei = (const int*)ei_raw;
        s = __ldg(ei + w);
        d = __ldg(ei + N_EDGES + w);
    }
    if ((unsigned long long)s >= N_NODES || (unsigned long long)d >= N_NODES) return;

    float4 v = *(const float4*)(g_msg + (size_t)s * DD + lane * 4);
    float* p = g_agg + (size_t)d * DD + lane * 4;
    asm volatile("red.global.add.v4.f32 [%0], {%1,%2,%3,%4};"
                 :: "l"(p), "f"(v.x), "f"(v.y), "f"(v.z), "f"(v.w)
                 : "memory");
}

// ---------------- launcher ----------------
extern "C" void kernel_launch(void* const* d_in, const int* in_sizes, int n_in,
                              void* d_out, int out_size)
{
    const float* x  = (const float*)d_in[0];
    const void*  ei = d_in[1];
    const float* Wi = (const float*)d_in[2];
    const float* bi = (const float*)d_in[3];
    const float* Wm = (const float*)d_in[4];
    const float* bm = (const float*)d_in[5];
    const float* Wu = (const float*)d_in[6];
    const float* bu = (const float*)d_in[7];
    float* out = (float*)d_out;

    cudaFuncSetAttribute(gemm_mma_kernel<0>, cudaFuncAttributeMaxDynamicSharedMemorySize, SM_TOTAL);
    cudaFuncSetAttribute(gemm_mma_kernel<1>, cudaFuncAttributeMaxDynamicSharedMemorySize, SM_TOTAL);

    float *msg, *agg;
    __nv_bfloat16* wb;
    cudaGetSymbolAddress((void**)&msg, g_msg);
    cudaGetSymbolAddress((void**)&agg, g_agg);
    cudaGetSymbolAddress((void**)&wb, g_wb);

    dim3 grid((N_NODES + 127) / 128);

    detect_idx_kernel<<<1, 1>>>((const int*)ei);
    conv_w_kernel<<<9, 256>>>(Wi, Wm, Wu);

    // state = relu(x @ Wi + bi)
    gemm_mma_kernel<0><<<grid, 256, SM_TOTAL>>>(x, wb, bi, out, N_NODES);

    for (int r = 0; r < ROUNDS; r++) {
        // message = relu(state @ Wm_r + bm_r)
        gemm_mma_kernel<0><<<grid, 256, SM_TOTAL>>>(out, wb + (size_t)(1 + r) * 32768,
                                                    bm + r * DD, msg, N_NODES);
        // aggregated = segment_sum(message[src], dst)
        zero_agg_kernel<<<(N_NODES * DD / 4) / 256, 256>>>();
        scatter_kernel<<<(N_EDGES * 32) / 256, 256>>>(ei);
        // state = state + relu(aggregated @ Wu_r + bu_r)
        gemm_mma_kernel<1><<<grid, 256, SM_TOTAL>>>(agg, wb + (size_t)(5 + r) * 32768,
                                                    bu + r * DD, out, N_NODES);
    }
}

// round 5
// speedup vs baseline: 1.4309x; 1.1818x over previous
#include <cuda_runtime.h>
#include <cuda_bf16.h>
#include <cstdint>

#define N_NODES 100000
#define N_EDGES 640000
#define DD      128
#define ROUNDS  4

// ---------------- scratch (allocation-free rule: __device__ globals) ----------------
__device__ __align__(16) float g_msg[N_NODES * DD];
__device__ __align__(16) float g_agg[N_NODES * DD];
// 9 weight matrices, transposed [n][k], bf16 split: hi (16384) + lo (16384) each
__device__ __align__(16) __nv_bfloat16 g_wb[9 * 2 * 16384];
__device__ int g_idx64;

// ---------------- edge_index dtype detection ----------------
__global__ void detect_idx_kernel(const int* __restrict__ ei32) {
    int is64 = 1;
    for (int i = 0; i < 32; i++) {
        int lo = ei32[2 * i];
        int hi = ei32[2 * i + 1];
        if (hi != 0 || lo < 0 || lo >= N_NODES) { is64 = 0; break; }
    }
    g_idx64 = is64;
}

// ---------------- weight precompute: transpose + bf16 split ----------------
__global__ void conv_w_kernel(const float* __restrict__ Wi,
                              const float* __restrict__ Wm,
                              const float* __restrict__ Wu) {
    int m = blockIdx.x;  // 0..8
    const float* W = (m == 0) ? Wi : (m <= 4 ? Wm + (m - 1) * DD * DD : Wu + (m - 5) * DD * DD);
    __nv_bfloat16* hi = g_wb + (size_t)m * 32768;
    __nv_bfloat16* lo = hi + 16384;
    for (int i = threadIdx.x; i < 2048; i += blockDim.x) {
        int nrow = i >> 4;
        int k8   = (i & 15) * 8;
        __align__(16) __nv_bfloat16 h[8], l[8];
#pragma unroll
        for (int j = 0; j < 8; j++) {
            float w = W[(size_t)(k8 + j) * DD + nrow];   // B[n][k] = W[k][n]
            __nv_bfloat16 hb = __float2bfloat16(w);
            h[j] = hb;
            l[j] = __float2bfloat16(w - __bfloat162float(hb));
        }
        *(uint4*)(hi + nrow * DD + k8) = *(const uint4*)h;
        *(uint4*)(lo + nrow * DD + k8) = *(const uint4*)l;
    }
}

// ---------------- helpers (base-target PTX only) ----------------
__device__ __forceinline__ uint32_t smem_u32(const void* p) {
    uint32_t a;
    asm("{ .reg .u64 t; cvta.to.shared.u64 t, %1; cvt.u32.u64 %0, t; }" : "=r"(a) : "l"(p));
    return a;
}
__device__ __forceinline__ void ldsm4(uint32_t& r0, uint32_t& r1, uint32_t& r2, uint32_t& r3,
                                      uint32_t addr) {
    asm volatile("ldmatrix.sync.aligned.m8n8.x4.shared.b16 {%0,%1,%2,%3}, [%4];"
                 : "=r"(r0), "=r"(r1), "=r"(r2), "=r"(r3) : "r"(addr));
}
__device__ __forceinline__ void mma_bf16(float& c0, float& c1, float& c2, float& c3,
                                         uint32_t a0, uint32_t a1, uint32_t a2, uint32_t a3,
                                         uint32_t b0, uint32_t b1) {
    asm volatile(
        "mma.sync.aligned.m16n8k16.row.col.f32.bf16.bf16.f32 "
        "{%0,%1,%2,%3}, {%4,%5,%6,%7}, {%8,%9}, {%0,%1,%2,%3};"
        : "+f"(c0), "+f"(c1), "+f"(c2), "+f"(c3)
        : "r"(a0), "r"(a1), "r"(a2), "r"(a3), "r"(b0), "r"(b1));
}

// ---------------- mma.sync GEMM (M-tile = 64, 2 CTAs/SM) ----------------
// SMEM: bias 512B | A_hi [64][136]bf16 | A_lo | B_hi [128][136]bf16 | B_lo
#define TILE_M  64
#define BSTR    136                       // 272B rows = 17*16B, conflict-free ldmatrix
#define A_TB    (TILE_M * BSTR * 2)       // 17408 B
#define B_TB    (128 * BSTR * 2)          // 34816 B
#define SM_BIAS 0
#define SM_AHI  512
#define SM_ALO  (SM_AHI + A_TB)
#define SM_BHI  (SM_ALO + A_TB)
#define SM_BLO  (SM_BHI + B_TB)
#define SM_TOTAL (SM_BLO + B_TB)          // 104960 B -> 2 CTAs/SM

template <int MODE>
__global__ __launch_bounds__(256, 2) void gemm_mma_kernel(
    const float* __restrict__ A,
    const __nv_bfloat16* __restrict__ wb,   // hi(16384) + lo(16384), [n][k]
    const float* __restrict__ bias,
    float* __restrict__ out,
    int n)
{
    extern __shared__ char smem[];
    const uint32_t sb = smem_u32(smem);
    const int tid = threadIdx.x, wid = tid >> 5, lane = tid & 31;
    const int wr = wid & 1, wc = wid >> 1;      // warp grid 2 (M) x 4 (N)
    const int m0 = blockIdx.x * TILE_M;

    if (tid < 128) *(float*)(smem + SM_BIAS + tid * 4) = bias[tid];

    // ---- weights: global [n][128] -> smem [n][BSTR] (hi and lo) ----
    {
        const uint4* srch = (const uint4*)wb;
        const uint4* srcl = (const uint4*)(wb + 16384);
#pragma unroll
        for (int i = tid; i < 2048; i += 256) {
            int row = i >> 4, c = i & 15;
            *(uint4*)(smem + SM_BHI + row * (BSTR * 2) + c * 16) = srch[row * 16 + c];
            *(uint4*)(smem + SM_BLO + row * (BSTR * 2) + c * 16) = srcl[row * 16 + c];
        }
    }

    // ---- A tile (64 rows): fp32 -> bf16 hi/lo ----
    for (int i = tid; i < TILE_M * 16; i += 256) {
        int r  = i >> 4;
        int k8 = (i & 15) * 8;
        int row = m0 + r;
        float v[8];
        if (row < n) {
            float4 u0 = *(const float4*)(A + (size_t)row * DD + k8);
            float4 u1 = *(const float4*)(A + (size_t)row * DD + k8 + 4);
            v[0] = u0.x; v[1] = u0.y; v[2] = u0.z; v[3] = u0.w;
            v[4] = u1.x; v[5] = u1.y; v[6] = u1.z; v[7] = u1.w;
        } else {
#pragma unroll
            for (int j = 0; j < 8; j++) v[j] = 0.f;
        }
        __align__(16) __nv_bfloat16 h[8], l[8];
#pragma unroll
        for (int j = 0; j < 8; j++) {
            __nv_bfloat16 hb = __float2bfloat16(v[j]);
            h[j] = hb;
            l[j] = __float2bfloat16(v[j] - __bfloat162float(hb));
        }
        *(uint4*)(smem + SM_AHI + r * (BSTR * 2) + k8 * 2) = *(const uint4*)h;
        *(uint4*)(smem + SM_ALO + r * (BSTR * 2) + k8 * 2) = *(const uint4*)l;
    }
    __syncthreads();

    // ---- mainloop: 8 k-steps x (hi*hi + hi*lo + lo*hi) ----
    float acc[2][4][4];                     // [mtile][ntile][reg]
#pragma unroll
    for (int t = 0; t < 2; t++)
#pragma unroll
        for (int j = 0; j < 4; j++)
#pragma unroll
            for (int q = 0; q < 4; q++)
                acc[t][j][q] = 0.f;

    const uint32_t a_row  = (uint32_t)(wr * 32 + (lane & 15));
    const uint32_t a_colh = (uint32_t)(lane >> 4);
    const uint32_t b_nrow = (uint32_t)(wc * 32 + (lane & 7) + ((lane >> 4) << 3));
    const uint32_t b_kh   = (uint32_t)((lane >> 3) & 1);

#pragma unroll
    for (int ks = 0; ks < 8; ks++) {
        uint32_t ah[2][4], al[2][4], bh[2][4], bl[2][4];
        const uint32_t kcol = (uint32_t)(ks * 16);
#pragma unroll
        for (int t = 0; t < 2; t++) {
            uint32_t off = (a_row + t * 16) * (BSTR * 2) + (kcol + a_colh * 8) * 2;
            ldsm4(ah[t][0], ah[t][1], ah[t][2], ah[t][3], sb + SM_AHI + off);
            ldsm4(al[t][0], al[t][1], al[t][2], al[t][3], sb + SM_ALO + off);
        }
#pragma unroll
        for (int p = 0; p < 2; p++) {
            uint32_t off = (b_nrow + p * 16) * (BSTR * 2) + (kcol + b_kh * 8) * 2;
            ldsm4(bh[p][0], bh[p][1], bh[p][2], bh[p][3], sb + SM_BHI + off);
            ldsm4(bl[p][0], bl[p][1], bl[p][2], bl[p][3], sb + SM_BLO + off);
        }
#pragma unroll
        for (int t = 0; t < 2; t++) {
#pragma unroll
            for (int j = 0; j < 4; j++) {
                uint32_t bh0 = bh[j >> 1][(j & 1) * 2], bh1 = bh[j >> 1][(j & 1) * 2 + 1];
                uint32_t bl0 = bl[j >> 1][(j & 1) * 2], bl1 = bl[j >> 1][(j & 1) * 2 + 1];
                float* c = acc[t][j];
                mma_bf16(c[0], c[1], c[2], c[3], ah[t][0], ah[t][1], ah[t][2], ah[t][3], bh0, bh1);
                mma_bf16(c[0], c[1], c[2], c[3], ah[t][0], ah[t][1], ah[t][2], ah[t][3], bl0, bl1);
                mma_bf16(c[0], c[1], c[2], c[3], al[t][0], al[t][1], al[t][2], al[t][3], bh0, bh1);
            }
        }
    }

    // ---- epilogue: bias + relu (+ residual) ----
    const float* bs = (const float*)(smem + SM_BIAS);
#pragma unroll
    for (int t = 0; t < 2; t++) {
        int row0 = m0 + wr * 32 + t * 16 + (lane >> 2);
#pragma unroll
        for (int half = 0; half < 2; half++) {
            int row = row0 + half * 8;
            if (row >= n) continue;
            float* orow = out + (size_t)row * DD;
#pragma unroll
            for (int j = 0; j < 4; j++) {
                int col = wc * 32 + j * 8 + (lane & 3) * 2;
                float v0 = acc[t][j][half * 2 + 0] + bs[col];
                float v1 = acc[t][j][half * 2 + 1] + bs[col + 1];
                v0 = v0 > 0.f ? v0 : 0.f;
                v1 = v1 > 0.f ? v1 : 0.f;
                if (MODE == 1) {
                    float2 o = *(const float2*)(orow + col);
                    v0 += o.x; v1 += o.y;
                }
                *(float2*)(orow + col) = make_float2(v0, v1);
            }
        }
    }
}

// ---------------- scatter phase ----------------
__global__ void zero_agg_kernel() {
    int i = blockIdx.x * blockDim.x + threadIdx.x;
    ((float4*)g_agg)[i] = make_float4(0.f, 0.f, 0.f, 0.f);
}

__global__ __launch_bounds__(256) void scatter_kernel(const void* __restrict__ ei_raw) {
    int w    = (blockIdx.x * 256 + threadIdx.x) >> 5;
    int lane = threadIdx.x & 31;
    if (w >= N_EDGES) return;

    long long s, d;
    if (__ldg(&g_idx64)) {
        const long long* ei = (const long long*)ei_raw;
        s = __ldg(ei + w);
        d = __ldg(ei + N_EDGES + w);
    } else {
        const int* ei = (const int*)ei_raw;
        s = __ldg(ei + w);
        d = __ldg(ei + N_EDGES + w);
    }
    if ((unsigned long long)s >= N_NODES || (unsigned long long)d >= N_NODES) return;

    float4 v = *(const float4*)(g_msg + (size_t)s * DD + lane * 4);
    float* p = g_agg + (size_t)d * DD + lane * 4;
    asm volatile("red.global.add.v4.f32 [%0], {%1,%2,%3,%4};"
                 :: "l"(p), "f"(v.x), "f"(v.y), "f"(v.z), "f"(v.w)
                 : "memory");
}

// ---------------- launcher ----------------
extern "C" void kernel_launch(void* const* d_in, const int* in_sizes, int n_in,
                              void* d_out, int out_size)
{
    const float* x  = (const float*)d_in[0];
    const void*  ei = d_in[1];
    const float* Wi = (const float*)d_in[2];
    const float* bi = (const float*)d_in[3];
    const float* Wm = (const float*)d_in[4];
    const float* bm = (const float*)d_in[5];
    const float* Wu = (const float*)d_in[6];
    const float* bu = (const float*)d_in[7];
    float* out = (float*)d_out;

    cudaFuncSetAttribute(gemm_mma_kernel<0>, cudaFuncAttributeMaxDynamicSharedMemorySize, SM_TOTAL);
    cudaFuncSetAttribute(gemm_mma_kernel<1>, cudaFuncAttributeMaxDynamicSharedMemorySize, SM_TOTAL);

    float *msg, *agg;
    __nv_bfloat16* wb;
    cudaGetSymbolAddress((void**)&msg, g_msg);
    cudaGetSymbolAddress((void**)&agg, g_agg);
    cudaGetSymbolAddress((void**)&wb, g_wb);

    dim3 grid((N_NODES + TILE_M - 1) / TILE_M);

    detect_idx_kernel<<<1, 1>>>((const int*)ei);
    conv_w_kernel<<<9, 256>>>(Wi, Wm, Wu);

    // state = relu(x @ Wi + bi)
    gemm_mma_kernel<0><<<grid, 256, SM_TOTAL>>>(x, wb, bi, out, N_NODES);

    for (int r = 0; r < ROUNDS; r++) {
        // message = relu(state @ Wm_r + bm_r)
        gemm_mma_kernel<0><<<grid, 256, SM_TOTAL>>>(out, wb + (size_t)(1 + r) * 32768,
                                                    bm + r * DD, msg, N_NODES);
        // aggregated = segment_sum(message[src], dst)
        zero_agg_kernel<<<(N_NODES * DD / 4) / 256, 256>>>();
        scatter_kernel<<<(N_EDGES * 32) / 256, 256>>>(ei);
        // state = state + relu(aggregated @ Wu_r + bu_r)
        gemm_mma_kernel<1><<<grid, 256, SM_TOTAL>>>(agg, wb + (size_t)(5 + r) * 32768,
                                                    bu + r * DD, out, N_NODES);
    }
}

// round 6
// speedup vs baseline: 1.8765x; 1.3114x over previous
#include <cuda_runtime.h>
#include <cuda_bf16.h>
#include <cstdint>

#define N_NODES 100000
#define N_EDGES 640000
#define DD      128
#define ROUNDS  4
#define SCAN_BLOCKS 98            // ceil(100000 / 1024)

// ---------------- scratch (allocation-free rule: __device__ globals) ----------------
__device__ __align__(16) float g_msg[N_NODES * DD];
__device__ __align__(16) float g_agg[N_NODES * DD];
__device__ __align__(16) __nv_bfloat16 g_wb[9 * 2 * 16384];
__device__ int g_idx64;
// CSR build scratch
__device__ int g_deg[N_NODES];
__device__ int g_off[N_NODES + 1];
__device__ int g_cur[N_NODES];
__device__ int g_srcs[N_EDGES];
__device__ int g_bsum[SCAN_BLOCKS];
__device__ int g_boff[SCAN_BLOCKS];

// ---------------- edge_index dtype detection ----------------
__global__ void detect_idx_kernel(const int* __restrict__ ei32) {
    int is64 = 1;
    for (int i = 0; i < 32; i++) {
        int lo = ei32[2 * i];
        int hi = ei32[2 * i + 1];
        if (hi != 0 || lo < 0 || lo >= N_NODES) { is64 = 0; break; }
    }
    g_idx64 = is64;
}

// ---------------- CSR build (once per call) ----------------
__global__ void hist_zero_kernel() {
    int i = blockIdx.x * blockDim.x + threadIdx.x;
    if (i < N_NODES) g_deg[i] = 0;
}

__device__ __forceinline__ int edge_dst(const void* ei_raw, int e) {
    if (g_idx64) return (int)((const long long*)ei_raw)[N_EDGES + e];
    return ((const int*)ei_raw)[N_EDGES + e];
}
__device__ __forceinline__ int edge_src(const void* ei_raw, int e) {
    if (g_idx64) return (int)((const long long*)ei_raw)[e];
    return ((const int*)ei_raw)[e];
}

__global__ void hist_kernel(const void* __restrict__ ei_raw) {
    int e = blockIdx.x * blockDim.x + threadIdx.x;
    if (e >= N_EDGES) return;
    int d = edge_dst(ei_raw, e);
    if ((unsigned)d < N_NODES) atomicAdd(&g_deg[d], 1);
}

// block-local exclusive scan over 1024 elements; write local offsets + block sum
__global__ void scan1_kernel() {
    __shared__ int ss[256];
    int b = blockIdx.x, t = threadIdx.x;
    int base = b * 1024 + t * 4;
    int v[4], tot = 0;
#pragma unroll
    for (int j = 0; j < 4; j++) {
        v[j] = (base + j < N_NODES) ? g_deg[base + j] : 0;
        tot += v[j];
    }
    ss[t] = tot;
    __syncthreads();
#pragma unroll
    for (int off = 1; off < 256; off <<= 1) {
        int x = (t >= off) ? ss[t - off] : 0;
        __syncthreads();
        ss[t] += x;
        __syncthreads();
    }
    int run = ss[t] - tot;   // exclusive prefix for this thread
#pragma unroll
    for (int j = 0; j < 4; j++) {
        if (base + j < N_NODES) g_off[base + j] = run;
        run += v[j];
    }
    if (t == 255) g_bsum[b] = ss[255];
}

__global__ void scan2_kernel() {
    __shared__ int ss[128];
    int t = threadIdx.x;
    int orig = (t < SCAN_BLOCKS) ? g_bsum[t] : 0;
    ss[t] = orig;
    __syncthreads();
#pragma unroll
    for (int off = 1; off < 128; off <<= 1) {
        int x = (t >= off) ? ss[t - off] : 0;
        __syncthreads();
        ss[t] += x;
        __syncthreads();
    }
    if (t < SCAN_BLOCKS) g_boff[t] = ss[t] - orig;
}

__global__ void scan3_kernel() {
    int i = blockIdx.x * blockDim.x + threadIdx.x;
    if (i < N_NODES) {
        int o = g_off[i] + g_boff[i >> 10];
        g_off[i] = o;
        g_cur[i] = o;
    }
    if (i == 0) g_off[N_NODES] = N_EDGES;
}

__global__ void fill_kernel(const void* __restrict__ ei_raw) {
    int e = blockIdx.x * blockDim.x + threadIdx.x;
    if (e >= N_EDGES) return;
    int d = edge_dst(ei_raw, e);
    int s = edge_src(ei_raw, e);
    if ((unsigned)d >= N_NODES || (unsigned)s >= N_NODES) return;
    int p = atomicAdd(&g_cur[d], 1);
    g_srcs[p] = s;
}

// ---------------- per-round aggregation: warp per dst node ----------------
__global__ __launch_bounds__(256) void aggregate_kernel() {
    int node = (blockIdx.x * 256 + threadIdx.x) >> 5;
    int lane = threadIdx.x & 31;
    if (node >= N_NODES) return;
    int beg = g_off[node], end = g_off[node + 1];
    float4 acc = make_float4(0.f, 0.f, 0.f, 0.f);
    int e = beg;
    for (; e + 1 < end; e += 2) {
        int s0 = g_srcs[e], s1 = g_srcs[e + 1];
        float4 v0 = *(const float4*)(g_msg + (size_t)s0 * DD + lane * 4);
        float4 v1 = *(const float4*)(g_msg + (size_t)s1 * DD + lane * 4);
        acc.x += v0.x; acc.y += v0.y; acc.z += v0.z; acc.w += v0.w;
        acc.x += v1.x; acc.y += v1.y; acc.z += v1.z; acc.w += v1.w;
    }
    if (e < end) {
        float4 v = *(const float4*)(g_msg + (size_t)g_srcs[e] * DD + lane * 4);
        acc.x += v.x; acc.y += v.y; acc.z += v.z; acc.w += v.w;
    }
    *(float4*)(g_agg + (size_t)node * DD + lane * 4) = acc;
}

// ---------------- weight precompute: transpose + bf16 split ----------------
__global__ void conv_w_kernel(const float* __restrict__ Wi,
                              const float* __restrict__ Wm,
                              const float* __restrict__ Wu) {
    int m = blockIdx.x;  // 0..8
    const float* W = (m == 0) ? Wi : (m <= 4 ? Wm + (m - 1) * DD * DD : Wu + (m - 5) * DD * DD);
    __nv_bfloat16* hi = g_wb + (size_t)m * 32768;
    __nv_bfloat16* lo = hi + 16384;
    for (int i = threadIdx.x; i < 2048; i += blockDim.x) {
        int nrow = i >> 4;
        int k8   = (i & 15) * 8;
        __align__(16) __nv_bfloat16 h[8], l[8];
#pragma unroll
        for (int j = 0; j < 8; j++) {
            float w = W[(size_t)(k8 + j) * DD + nrow];   // B[n][k] = W[k][n]
            __nv_bfloat16 hb = __float2bfloat16(w);
            h[j] = hb;
            l[j] = __float2bfloat16(w - __bfloat162float(hb));
        }
        *(uint4*)(hi + nrow * DD + k8) = *(const uint4*)h;
        *(uint4*)(lo + nrow * DD + k8) = *(const uint4*)l;
    }
}

// ---------------- helpers (base-target PTX only) ----------------
__device__ __forceinline__ uint32_t smem_u32(const void* p) {
    uint32_t a;
    asm("{ .reg .u64 t; cvta.to.shared.u64 t, %1; cvt.u32.u64 %0, t; }" : "=r"(a) : "l"(p));
    return a;
}
__device__ __forceinline__ void ldsm4(uint32_t& r0, uint32_t& r1, uint32_t& r2, uint32_t& r3,
                                      uint32_t addr) {
    asm volatile("ldmatrix.sync.aligned.m8n8.x4.shared.b16 {%0,%1,%2,%3}, [%4];"
                 : "=r"(r0), "=r"(r1), "=r"(r2), "=r"(r3) : "r"(addr));
}
__device__ __forceinline__ void mma_bf16(float& c0, float& c1, float& c2, float& c3,
                                         uint32_t a0, uint32_t a1, uint32_t a2, uint32_t a3,
                                         uint32_t b0, uint32_t b1) {
    asm volatile(
        "mma.sync.aligned.m16n8k16.row.col.f32.bf16.bf16.f32 "
        "{%0,%1,%2,%3}, {%4,%5,%6,%7}, {%8,%9}, {%0,%1,%2,%3};"
        : "+f"(c0), "+f"(c1), "+f"(c2), "+f"(c3)
        : "r"(a0), "r"(a1), "r"(a2), "r"(a3), "r"(b0), "r"(b1));
}

// ---------------- mma.sync GEMM (M-tile = 64, 2 CTAs/SM) ----------------
#define TILE_M  64
#define BSTR    136
#define A_TB    (TILE_M * BSTR * 2)       // 17408 B
#define B_TB    (128 * BSTR * 2)          // 34816 B
#define SM_BIAS 0
#define SM_AHI  512
#define SM_ALO  (SM_AHI + A_TB)
#define SM_BHI  (SM_ALO + A_TB)
#define SM_BLO  (SM_BHI + B_TB)
#define SM_TOTAL (SM_BLO + B_TB)          // 104960 B -> 2 CTAs/SM

template <int MODE>
__global__ __launch_bounds__(256, 2) void gemm_mma_kernel(
    const float* __restrict__ A,
    const __nv_bfloat16* __restrict__ wb,
    const float* __restrict__ bias,
    float* __restrict__ out,
    int n)
{
    extern __shared__ char smem[];
    const uint32_t sb = smem_u32(smem);
    const int tid = threadIdx.x, wid = tid >> 5, lane = tid & 31;
    const int wr = wid & 1, wc = wid >> 1;      // warp grid 2 (M) x 4 (N)
    const int m0 = blockIdx.x * TILE_M;

    if (tid < 128) *(float*)(smem + SM_BIAS + tid * 4) = bias[tid];

    {
        const uint4* srch = (const uint4*)wb;
        const uint4* srcl = (const uint4*)(wb + 16384);
#pragma unroll
        for (int i = tid; i < 2048; i += 256) {
            int row = i >> 4, c = i & 15;
            *(uint4*)(smem + SM_BHI + row * (BSTR * 2) + c * 16) = srch[row * 16 + c];
            *(uint4*)(smem + SM_BLO + row * (BSTR * 2) + c * 16) = srcl[row * 16 + c];
        }
    }

    for (int i = tid; i < TILE_M * 16; i += 256) {
        int r  = i >> 4;
        int k8 = (i & 15) * 8;
        int row = m0 + r;
        float v[8];
        if (row < n) {
            float4 u0 = *(const float4*)(A + (size_t)row * DD + k8);
            float4 u1 = *(const float4*)(A + (size_t)row * DD + k8 + 4);
            v[0] = u0.x; v[1] = u0.y; v[2] = u0.z; v[3] = u0.w;
            v[4] = u1.x; v[5] = u1.y; v[6] = u1.z; v[7] = u1.w;
        } else {
#pragma unroll
            for (int j = 0; j < 8; j++) v[j] = 0.f;
        }
        __align__(16) __nv_bfloat16 h[8], l[8];
#pragma unroll
        for (int j = 0; j < 8; j++) {
            __nv_bfloat16 hb = __float2bfloat16(v[j]);
            h[j] = hb;
            l[j] = __float2bfloat16(v[j] - __bfloat162float(hb));
        }
        *(uint4*)(smem + SM_AHI + r * (BSTR * 2) + k8 * 2) = *(const uint4*)h;
        *(uint4*)(smem + SM_ALO + r * (BSTR * 2) + k8 * 2) = *(const uint4*)l;
    }
    __syncthreads();

    float acc[2][4][4];
#pragma unroll
    for (int t = 0; t < 2; t++)
#pragma unroll
        for (int j = 0; j < 4; j++)
#pragma unroll
            for (int q = 0; q < 4; q++)
                acc[t][j][q] = 0.f;

    const uint32_t a_row  = (uint32_t)(wr * 32 + (lane & 15));
    const uint32_t a_colh = (uint32_t)(lane >> 4);
    const uint32_t b_nrow = (uint32_t)(wc * 32 + (lane & 7) + ((lane >> 4) << 3));
    const uint32_t b_kh   = (uint32_t)((lane >> 3) & 1);

#pragma unroll
    for (int ks = 0; ks < 8; ks++) {
        uint32_t ah[2][4], al[2][4], bh[2][4], bl[2][4];
        const uint32_t kcol = (uint32_t)(ks * 16);
#pragma unroll
        for (int t = 0; t < 2; t++) {
            uint32_t off = (a_row + t * 16) * (BSTR * 2) + (kcol + a_colh * 8) * 2;
            ldsm4(ah[t][0], ah[t][1], ah[t][2], ah[t][3], sb + SM_AHI + off);
            ldsm4(al[t][0], al[t][1], al[t][2], al[t][3], sb + SM_ALO + off);
        }
#pragma unroll
        for (int p = 0; p < 2; p++) {
            uint32_t off = (b_nrow + p * 16) * (BSTR * 2) + (kcol + b_kh * 8) * 2;
            ldsm4(bh[p][0], bh[p][1], bh[p][2], bh[p][3], sb + SM_BHI + off);
            ldsm4(bl[p][0], bl[p][1], bl[p][2], bl[p][3], sb + SM_BLO + off);
        }
#pragma unroll
        for (int t = 0; t < 2; t++) {
#pragma unroll
            for (int j = 0; j < 4; j++) {
                uint32_t bh0 = bh[j >> 1][(j & 1) * 2], bh1 = bh[j >> 1][(j & 1) * 2 + 1];
                uint32_t bl0 = bl[j >> 1][(j & 1) * 2], bl1 = bl[j >> 1][(j & 1) * 2 + 1];
                float* c = acc[t][j];
                mma_bf16(c[0], c[1], c[2], c[3], ah[t][0], ah[t][1], ah[t][2], ah[t][3], bh0, bh1);
                mma_bf16(c[0], c[1], c[2], c[3], ah[t][0], ah[t][1], ah[t][2], ah[t][3], bl0, bl1);
                mma_bf16(c[0], c[1], c[2], c[3], al[t][0], al[t][1], al[t][2], al[t][3], bh0, bh1);
            }
        }
    }

    const float* bs = (const float*)(smem + SM_BIAS);
#pragma unroll
    for (int t = 0; t < 2; t++) {
        int row0 = m0 + wr * 32 + t * 16 + (lane >> 2);
#pragma unroll
        for (int half = 0; half < 2; half++) {
            int row = row0 + half * 8;
            if (row >= n) continue;
            float* orow = out + (size_t)row * DD;
#pragma unroll
            for (int j = 0; j < 4; j++) {
                int col = wc * 32 + j * 8 + (lane & 3) * 2;
                float v0 = acc[t][j][half * 2 + 0] + bs[col];
                float v1 = acc[t][j][half * 2 + 1] + bs[col + 1];
                v0 = v0 > 0.f ? v0 : 0.f;
                v1 = v1 > 0.f ? v1 : 0.f;
                if (MODE == 1) {
                    float2 o = *(const float2*)(orow + col);
                    v0 += o.x; v1 += o.y;
                }
                *(float2*)(orow + col) = make_float2(v0, v1);
            }
        }
    }
}

// ---------------- launcher ----------------
extern "C" void kernel_launch(void* const* d_in, const int* in_sizes, int n_in,
                              void* d_out, int out_size)
{
    const float* x  = (const float*)d_in[0];
    const void*  ei = d_in[1];
    const float* Wi = (const float*)d_in[2];
    const float* bi = (const float*)d_in[3];
    const float* Wm = (const float*)d_in[4];
    const float* bm = (const float*)d_in[5];
    const float* Wu = (const float*)d_in[6];
    const float* bu = (const float*)d_in[7];
    float* out = (float*)d_out;

    cudaFuncSetAttribute(gemm_mma_kernel<0>, cudaFuncAttributeMaxDynamicSharedMemorySize, SM_TOTAL);
    cudaFuncSetAttribute(gemm_mma_kernel<1>, cudaFuncAttributeMaxDynamicSharedMemorySize, SM_TOTAL);

    float *msg, *agg;
    __nv_bfloat16* wb;
    cudaGetSymbolAddress((void**)&msg, g_msg);
    cudaGetSymbolAddress((void**)&agg, g_agg);
    cudaGetSymbolAddress((void**)&wb, g_wb);

    dim3 grid((N_NODES + TILE_M - 1) / TILE_M);

    detect_idx_kernel<<<1, 1>>>((const int*)ei);
    conv_w_kernel<<<9, 256>>>(Wi, Wm, Wu);

    // ---- CSR build (once per call) ----
    hist_zero_kernel<<<(N_NODES + 255) / 256, 256>>>();
    hist_kernel<<<(N_EDGES + 255) / 256, 256>>>(ei);
    scan1_kernel<<<SCAN_BLOCKS, 256>>>();
    scan2_kernel<<<1, 128>>>();
    scan3_kernel<<<(N_NODES + 255) / 256, 256>>>();
    fill_kernel<<<(N_EDGES + 255) / 256, 256>>>(ei);

    // state = relu(x @ Wi + bi)
    gemm_mma_kernel<0><<<grid, 256, SM_TOTAL>>>(x, wb, bi, out, N_NODES);

    for (int r = 0; r < ROUNDS; r++) {
        // message = relu(state @ Wm_r + bm_r)
        gemm_mma_kernel<0><<<grid, 256, SM_TOTAL>>>(out, wb + (size_t)(1 + r) * 32768,
                                                    bm + r * DD, msg, N_NODES);
        // aggregated = segment_sum(message[src], dst)  (CSR, no atomics)
        aggregate_kernel<<<(N_NODES * 32 + 255) / 256, 256>>>();
        // state = state + relu(aggregated @ Wu_r + bu_r)
        gemm_mma_kernel<1><<<grid, 256, SM_TOTAL>>>(agg, wb + (size_t)(5 + r) * 32768,
                                                    bu + r * DD, out, N_NODES);
    }
}

// round 7
// speedup vs baseline: 1.9229x; 1.0247x over previous
#include <cuda_runtime.h>
#include <cuda_bf16.h>
#include <cstdint>

#define N_NODES 100000
#define N_EDGES 640000
#define DD      128
#define ROUNDS  4
#define SCAN_BLOCKS 98            // ceil(100000 / 1024)

// ---------------- scratch (allocation-free rule: __device__ globals) ----------------
__device__ __align__(16) float g_msg[N_NODES * DD];
__device__ __align__(16) float g_agg[N_NODES * DD];
__device__ __align__(16) __nv_bfloat16 g_wb[9 * 2 * 16384];
__device__ int g_idx64;
// CSR build scratch
__device__ int g_deg[N_NODES];
__device__ int g_off[N_NODES + 1];
__device__ int g_cur[N_NODES];
__device__ int g_srcs[N_EDGES];
__device__ int g_bsum[SCAN_BLOCKS];
__device__ int g_boff[SCAN_BLOCKS];

// ---------------- edge_index dtype detection ----------------
__global__ void detect_idx_kernel(const int* __restrict__ ei32) {
    int is64 = 1;
    for (int i = 0; i < 32; i++) {
        int lo = ei32[2 * i];
        int hi = ei32[2 * i + 1];
        if (hi != 0 || lo < 0 || lo >= N_NODES) { is64 = 0; break; }
    }
    g_idx64 = is64;
}

// ---------------- CSR build (once per call) ----------------
__global__ void hist_zero_kernel() {
    int i = blockIdx.x * blockDim.x + threadIdx.x;
    if (i < N_NODES) g_deg[i] = 0;
}

__device__ __forceinline__ int edge_dst(const void* ei_raw, int e) {
    if (g_idx64) return (int)((const long long*)ei_raw)[N_EDGES + e];
    return ((const int*)ei_raw)[N_EDGES + e];
}
__device__ __forceinline__ int edge_src(const void* ei_raw, int e) {
    if (g_idx64) return (int)((const long long*)ei_raw)[e];
    return ((const int*)ei_raw)[e];
}

__global__ void hist_kernel(const void* __restrict__ ei_raw) {
    int e = blockIdx.x * blockDim.x + threadIdx.x;
    if (e >= N_EDGES) return;
    int d = edge_dst(ei_raw, e);
    if ((unsigned)d < N_NODES) atomicAdd(&g_deg[d], 1);
}

__global__ void scan1_kernel() {
    __shared__ int ss[256];
    int b = blockIdx.x, t = threadIdx.x;
    int base = b * 1024 + t * 4;
    int v[4], tot = 0;
#pragma unroll
    for (int j = 0; j < 4; j++) {
        v[j] = (base + j < N_NODES) ? g_deg[base + j] : 0;
        tot += v[j];
    }
    ss[t] = tot;
    __syncthreads();
#pragma unroll
    for (int off = 1; off < 256; off <<= 1) {
        int x = (t >= off) ? ss[t - off] : 0;
        __syncthreads();
        ss[t] += x;
        __syncthreads();
    }
    int run = ss[t] - tot;
#pragma unroll
    for (int j = 0; j < 4; j++) {
        if (base + j < N_NODES) g_off[base + j] = run;
        run += v[j];
    }
    if (t == 255) g_bsum[b] = ss[255];
}

__global__ void scan2_kernel() {
    __shared__ int ss[128];
    int t = threadIdx.x;
    int orig = (t < SCAN_BLOCKS) ? g_bsum[t] : 0;
    ss[t] = orig;
    __syncthreads();
#pragma unroll
    for (int off = 1; off < 128; off <<= 1) {
        int x = (t >= off) ? ss[t - off] : 0;
        __syncthreads();
        ss[t] += x;
        __syncthreads();
    }
    if (t < SCAN_BLOCKS) g_boff[t] = ss[t] - orig;
}

__global__ void scan3_kernel() {
    int i = blockIdx.x * blockDim.x + threadIdx.x;
    if (i < N_NODES) {
        int o = g_off[i] + g_boff[i >> 10];
        g_off[i] = o;
        g_cur[i] = o;
    }
    if (i == 0) g_off[N_NODES] = N_EDGES;
}

__global__ void fill_kernel(const void* __restrict__ ei_raw) {
    int e = blockIdx.x * blockDim.x + threadIdx.x;
    if (e >= N_EDGES) return;
    int d = edge_dst(ei_raw, e);
    int s = edge_src(ei_raw, e);
    if ((unsigned)d >= N_NODES || (unsigned)s >= N_NODES) return;
    int p = atomicAdd(&g_cur[d], 1);
    g_srcs[p] = s;
}

// ---------------- per-round aggregation: warp per dst node ----------------
__global__ __launch_bounds__(256) void aggregate_kernel() {
    int node = (blockIdx.x * 256 + threadIdx.x) >> 5;
    int lane = threadIdx.x & 31;
    if (node >= N_NODES) return;
    int beg = g_off[node], end = g_off[node + 1];
    float4 acc = make_float4(0.f, 0.f, 0.f, 0.f);
    int e = beg;
    for (; e + 1 < end; e += 2) {
        int s0 = g_srcs[e], s1 = g_srcs[e + 1];
        float4 v0 = *(const float4*)(g_msg + (size_t)s0 * DD + lane * 4);
        float4 v1 = *(const float4*)(g_msg + (size_t)s1 * DD + lane * 4);
        acc.x += v0.x; acc.y += v0.y; acc.z += v0.z; acc.w += v0.w;
        acc.x += v1.x; acc.y += v1.y; acc.z += v1.z; acc.w += v1.w;
    }
    if (e < end) {
        float4 v = *(const float4*)(g_msg + (size_t)g_srcs[e] * DD + lane * 4);
        acc.x += v.x; acc.y += v.y; acc.z += v.z; acc.w += v.w;
    }
    *(float4*)(g_agg + (size_t)node * DD + lane * 4) = acc;
}

// ---------------- weight precompute: transpose + bf16 split ----------------
__global__ void conv_w_kernel(const float* __restrict__ Wi,
                              const float* __restrict__ Wm,
                              const float* __restrict__ Wu) {
    int m = blockIdx.x;  // 0..8
    const float* W = (m == 0) ? Wi : (m <= 4 ? Wm + (m - 1) * DD * DD : Wu + (m - 5) * DD * DD);
    __nv_bfloat16* hi = g_wb + (size_t)m * 32768;
    __nv_bfloat16* lo = hi + 16384;
    for (int i = threadIdx.x; i < 2048; i += blockDim.x) {
        int nrow = i >> 4;
        int k8   = (i & 15) * 8;
        __align__(16) __nv_bfloat16 h[8], l[8];
#pragma unroll
        for (int j = 0; j < 8; j++) {
            float w = W[(size_t)(k8 + j) * DD + nrow];   // B[n][k] = W[k][n]
            __nv_bfloat16 hb = __float2bfloat16(w);
            h[j] = hb;
            l[j] = __float2bfloat16(w - __bfloat162float(hb));
        }
        *(uint4*)(hi + nrow * DD + k8) = *(const uint4*)h;
        *(uint4*)(lo + nrow * DD + k8) = *(const uint4*)l;
    }
}

// ---------------- helpers (base-target PTX only) ----------------
__device__ __forceinline__ uint32_t smem_u32(const void* p) {
    uint32_t a;
    asm("{ .reg .u64 t; cvta.to.shared.u64 t, %1; cvt.u32.u64 %0, t; }" : "=r"(a) : "l"(p));
    return a;
}
__device__ __forceinline__ void ldsm4(uint32_t* r, uint32_t addr) {
    asm volatile("ldmatrix.sync.aligned.m8n8.x4.shared.b16 {%0,%1,%2,%3}, [%4];"
                 : "=r"(r[0]), "=r"(r[1]), "=r"(r[2]), "=r"(r[3]) : "r"(addr));
}
__device__ __forceinline__ void mma_bf16(float* c,
                                         const uint32_t* a, uint32_t b0, uint32_t b1) {
    asm volatile(
        "mma.sync.aligned.m16n8k16.row.col.f32.bf16.bf16.f32 "
        "{%0,%1,%2,%3}, {%4,%5,%6,%7}, {%8,%9}, {%0,%1,%2,%3};"
        : "+f"(c[0]), "+f"(c[1]), "+f"(c[2]), "+f"(c[3])
        : "r"(a[0]), "r"(a[1]), "r"(a[2]), "r"(a[3]), "r"(b0), "r"(b1));
}
__device__ __forceinline__ void cp_async16(uint32_t smem_addr, const void* gptr) {
    asm volatile("cp.async.ca.shared.global [%0], [%1], 16;"
                 :: "r"(smem_addr), "l"(gptr) : "memory");
}

// ---------------- mma.sync GEMM (M-tile = 64, 2 CTAs/SM, pipelined) ----------------
#define TILE_M  64
#define BSTR    136
#define A_TB    (TILE_M * BSTR * 2)       // 17408 B
#define B_TB    (128 * BSTR * 2)          // 34816 B
#define SM_BIAS 0
#define SM_AHI  512
#define SM_ALO  (SM_AHI + A_TB)
#define SM_BHI  (SM_ALO + A_TB)
#define SM_BLO  (SM_BHI + B_TB)
#define SM_TOTAL (SM_BLO + B_TB)          // 104960 B -> 2 CTAs/SM

template <int MODE>
__global__ __launch_bounds__(256, 2) void gemm_mma_kernel(
    const float* __restrict__ A,
    const __nv_bfloat16* __restrict__ wb,
    const float* __restrict__ bias,
    float* __restrict__ out,
    int n)
{
    extern __shared__ char smem[];
    const uint32_t sb = smem_u32(smem);
    const int tid = threadIdx.x, wid = tid >> 5, lane = tid & 31;
    const int wr = wid & 1, wc = wid >> 1;      // warp grid 2 (M) x 4 (N)
    const int m0 = blockIdx.x * TILE_M;

    if (tid < 128) *(float*)(smem + SM_BIAS + tid * 4) = bias[tid];

    // ---- B tiles via cp.async (overlaps with A conversion below) ----
    {
        const uint4* srch = (const uint4*)wb;
        const uint4* srcl = (const uint4*)(wb + 16384);
#pragma unroll
        for (int i = tid; i < 2048; i += 256) {
            int row = i >> 4, c = i & 15;
            uint32_t doff = (uint32_t)(row * (BSTR * 2) + c * 16);
            cp_async16(sb + SM_BHI + doff, srch + row * 16 + c);
            cp_async16(sb + SM_BLO + doff, srcl + row * 16 + c);
        }
        asm volatile("cp.async.commit_group;" ::: "memory");
    }

    // ---- A tile (64 rows): fp32 -> bf16 hi/lo ----
    for (int i = tid; i < TILE_M * 16; i += 256) {
        int r  = i >> 4;
        int k8 = (i & 15) * 8;
        int row = m0 + r;
        float v[8];
        if (row < n) {
            float4 u0 = *(const float4*)(A + (size_t)row * DD + k8);
            float4 u1 = *(const float4*)(A + (size_t)row * DD + k8 + 4);
            v[0] = u0.x; v[1] = u0.y; v[2] = u0.z; v[3] = u0.w;
            v[4] = u1.x; v[5] = u1.y; v[6] = u1.z; v[7] = u1.w;
        } else {
#pragma unroll
            for (int j = 0; j < 8; j++) v[j] = 0.f;
        }
        __align__(16) __nv_bfloat16 h[8], l[8];
#pragma unroll
        for (int j = 0; j < 8; j++) {
            __nv_bfloat16 hb = __float2bfloat16(v[j]);
            h[j] = hb;
            l[j] = __float2bfloat16(v[j] - __bfloat162float(hb));
        }
        *(uint4*)(smem + SM_AHI + r * (BSTR * 2) + k8 * 2) = *(const uint4*)h;
        *(uint4*)(smem + SM_ALO + r * (BSTR * 2) + k8 * 2) = *(const uint4*)l;
    }
    asm volatile("cp.async.wait_group 0;" ::: "memory");
    __syncthreads();

    float acc[2][4][4];
#pragma unroll
    for (int t = 0; t < 2; t++)
#pragma unroll
        for (int j = 0; j < 4; j++)
#pragma unroll
            for (int q = 0; q < 4; q++)
                acc[t][j][q] = 0.f;

    const uint32_t a_row  = (uint32_t)(wr * 32 + (lane & 15));
    const uint32_t a_colh = (uint32_t)(lane >> 4);
    const uint32_t b_nrow = (uint32_t)(wc * 32 + (lane & 7) + ((lane >> 4) << 3));
    const uint32_t b_kh   = (uint32_t)((lane >> 3) & 1);

    // double-buffered fragments: [buf][tile][reg]
    uint32_t ah[2][2][4], al[2][2][4], bh[2][2][4], bl[2][2][4];

#define LOAD_K(ks_, buf_)                                                          \
    {                                                                              \
        const uint32_t kcol = (uint32_t)((ks_) * 16);                              \
        _Pragma("unroll")                                                          \
        for (int t = 0; t < 2; t++) {                                              \
            uint32_t off = (a_row + t * 16) * (BSTR * 2) + (kcol + a_colh * 8) * 2;\
            ldsm4(ah[buf_][t], sb + SM_AHI + off);                                 \
            ldsm4(al[buf_][t], sb + SM_ALO + off);                                 \
        }                                                                          \
        _Pragma("unroll")                                                          \
        for (int p = 0; p < 2; p++) {                                              \
            uint32_t off = (b_nrow + p * 16) * (BSTR * 2) + (kcol + b_kh * 8) * 2; \
            ldsm4(bh[buf_][p], sb + SM_BHI + off);                                 \
            ldsm4(bl[buf_][p], sb + SM_BLO + off);                                 \
        }                                                                          \
    }

    LOAD_K(0, 0)
#pragma unroll
    for (int ks = 0; ks < 8; ks++) {
        const int cur = ks & 1;
        if (ks < 7) LOAD_K(ks + 1, cur ^ 1)
#pragma unroll
        for (int t = 0; t < 2; t++) {
#pragma unroll
            for (int j = 0; j < 4; j++) {
                uint32_t bh0 = bh[cur][j >> 1][(j & 1) * 2], bh1 = bh[cur][j >> 1][(j & 1) * 2 + 1];
                uint32_t bl0 = bl[cur][j >> 1][(j & 1) * 2], bl1 = bl[cur][j >> 1][(j & 1) * 2 + 1];
                float* c = acc[t][j];
                mma_bf16(c, ah[cur][t], bh0, bh1);
                mma_bf16(c, ah[cur][t], bl0, bl1);
                mma_bf16(c, al[cur][t], bh0, bh1);
            }
        }
    }
#undef LOAD_K

    // ---- epilogue: bias + relu (+ residual) ----
    const float* bs = (const float*)(smem + SM_BIAS);
#pragma unroll
    for (int t = 0; t < 2; t++) {
        int row0 = m0 + wr * 32 + t * 16 + (lane >> 2);
#pragma unroll
        for (int half = 0; half < 2; half++) {
            int row = row0 + half * 8;
            if (row >= n) continue;
            float* orow = out + (size_t)row * DD;
#pragma unroll
            for (int j = 0; j < 4; j++) {
                int col = wc * 32 + j * 8 + (lane & 3) * 2;
                float v0 = acc[t][j][half * 2 + 0] + bs[col];
                float v1 = acc[t][j][half * 2 + 1] + bs[col + 1];
                v0 = v0 > 0.f ? v0 : 0.f;
                v1 = v1 > 0.f ? v1 : 0.f;
                if (MODE == 1) {
                    float2 o = *(const float2*)(orow + col);
                    v0 += o.x; v1 += o.y;
                }
                *(float2*)(orow + col) = make_float2(v0, v1);
            }
        }
    }
}

// ---------------- launcher ----------------
extern "C" void kernel_launch(void* const* d_in, const int* in_sizes, int n_in,
                              void* d_out, int out_size)
{
    const float* x  = (const float*)d_in[0];
    const void*  ei = d_in[1];
    const float* Wi = (const float*)d_in[2];
    const float* bi = (const float*)d_in[3];
    const float* Wm = (const float*)d_in[4];
    const float* bm = (const float*)d_in[5];
    const float* Wu = (const float*)d_in[6];
    const float* bu = (const float*)d_in[7];
    float* out = (float*)d_out;

    cudaFuncSetAttribute(gemm_mma_kernel<0>, cudaFuncAttributeMaxDynamicSharedMemorySize, SM_TOTAL);
    cudaFuncSetAttribute(gemm_mma_kernel<1>, cudaFuncAttributeMaxDynamicSharedMemorySize, SM_TOTAL);

    float *msg, *agg;
    __nv_bfloat16* wb;
    cudaGetSymbolAddress((void**)&msg, g_msg);
    cudaGetSymbolAddress((void**)&agg, g_agg);
    cudaGetSymbolAddress((void**)&wb, g_wb);

    dim3 grid((N_NODES + TILE_M - 1) / TILE_M);

    detect_idx_kernel<<<1, 1>>>((const int*)ei);
    conv_w_kernel<<<9, 256>>>(Wi, Wm, Wu);

    // ---- CSR build (once per call) ----
    hist_zero_kernel<<<(N_NODES + 255) / 256, 256>>>();
    hist_kernel<<<(N_EDGES + 255) / 256, 256>>>(ei);
    scan1_kernel<<<SCAN_BLOCKS, 256>>>();
    scan2_kernel<<<1, 128>>>();
    scan3_kernel<<<(N_NODES + 255) / 256, 256>>>();
    fill_kernel<<<(N_EDGES + 255) / 256, 256>>>(ei);

    // state = relu(x @ Wi + bi)
    gemm_mma_kernel<0><<<grid, 256, SM_TOTAL>>>(x, wb, bi, out, N_NODES);

    for (int r = 0; r < ROUNDS; r++) {
        // message = relu(state @ Wm_r + bm_r)
        gemm_mma_kernel<0><<<grid, 256, SM_TOTAL>>>(out, wb + (size_t)(1 + r) * 32768,
                                                    bm + r * DD, msg, N_NODES);
        // aggregated = segment_sum(message[src], dst)  (CSR, no atomics)
        aggregate_kernel<<<(N_NODES * 32 + 255) / 256, 256>>>();
        // state = state + relu(aggregated @ Wu_r + bu_r)
        gemm_mma_kernel<1><<<grid, 256, SM_TOTAL>>>(agg, wb + (size_t)(5 + r) * 32768,
                                                    bu + r * DD, out, N_NODES);
    }
}